// round 1
// baseline (speedup 1.0000x reference)
#include <cuda_runtime.h>

// ---------------------------------------------------------------------------
// QBWBottleneck: quantized ResNet bottleneck block, fp32 implicit-GEMM SIMT.
//
// x[32,256,56,56]
//  conv1 1x1 s1 256->128 +BN+fq+relu  -> o1 [32,128,56,56]   (g_buf1)
//  conv2 3x3 s2 128->128 +BN+fq+relu  -> o2 [32,128,28,28]   (g_buf2)
//  conv3 1x1 s1 128->512 +BN+fq       -> t3 [32,512,28,28]   (g_buf1 reused)
//  sc    1x1 s2 256->512 +BN+fq ; out = relu(t3 + sc)        (d_out)
//
// All accumulation in fp32 FFMA (fake-quant rounding boundaries make low
// precision tensor-core paths fail the 1e-3 rel-err gate).
// ---------------------------------------------------------------------------

#define EPSBN 1e-5f

// 32*128*3136 == 32*512*784 == 12,845,056 floats (51.4 MB)
__device__ float g_buf1[12845056];
// 32*128*784 = 3,211,264 floats (12.8 MB)
__device__ float g_buf2[3211264];

__device__ __forceinline__ float fq(float y, float s) {
    float q = rintf(y / s);                 // round-half-to-even == jnp.round
    q = fminf(fmaxf(q, -127.f), 127.f);
    return q * s;
}

// Shared GEMM tile geometry: BM=BN=128, BK=16, 256 threads, 8x8 per thread.

#define GEMM_COMPUTE_STEP()                                                    \
    __syncthreads();                                                           \
    _Pragma("unroll")                                                          \
    for (int kk = 0; kk < 16; ++kk) {                                          \
        float a[8], bv[8];                                                     \
        _Pragma("unroll")                                                      \
        for (int i = 0; i < 8; ++i) a[i] = As[kk][ty * 8 + i];                 \
        _Pragma("unroll")                                                      \
        for (int j = 0; j < 8; ++j) bv[j] = Bs[kk][tx * 8 + j];                \
        _Pragma("unroll")                                                      \
        for (int i = 0; i < 8; ++i)                                            \
            _Pragma("unroll")                                                  \
            for (int j = 0; j < 8; ++j)                                        \
                acc[i][j] = fmaf(a[i], bv[j], acc[i][j]);                      \
    }                                                                          \
    __syncthreads();

// ---------------------------------------------------------------------------
// Kernel 1: conv1 1x1 s1.  C[co=128][j=100352] = W1[128,256] * X[256, j]
// j = n*3136 + p ; X element = x[n*802816 + ci*3136 + p]
// ---------------------------------------------------------------------------
__global__ __launch_bounds__(256, 2)
void conv1_k(const float* __restrict__ x, const float* __restrict__ w,
             const float* __restrict__ gg, const float* __restrict__ bb,
             const float* __restrict__ mm, const float* __restrict__ vv,
             const float* __restrict__ ss)
{
    __shared__ float As[16][128];
    __shared__ float Bs[16][128];
    const int t  = threadIdx.x;
    const int tx = t & 15, ty = t >> 4;
    const int jcol = t & 127, krow = t >> 7;      // B-loader: column, k-half
    const int jg = blockIdx.x * 128 + jcol;
    const int n  = jg / 3136, p = jg - n * 3136;
    const float* xb = x + n * 802816 + p;
    const int ai = t >> 1;                        // A-loader: row 0..127
    const int ak = (t & 1) * 8;                   // k sub-offset 0/8

    float acc[8][8];
#pragma unroll
    for (int i = 0; i < 8; ++i)
#pragma unroll
        for (int j = 0; j < 8; ++j) acc[i][j] = 0.f;

    for (int k0 = 0; k0 < 256; k0 += 16) {
        const float* wp = w + ai * 256 + k0 + ak;
#pragma unroll
        for (int r = 0; r < 8; ++r) As[ak + r][ai] = wp[r];
        const float* xp = xb + (k0 + krow * 8) * 3136;
#pragma unroll
        for (int r = 0; r < 8; ++r) Bs[krow * 8 + r][jcol] = xp[r * 3136];
        GEMM_COMPUTE_STEP();
    }

    const float s = *ss;
    float inv_[8], bia_[8];
#pragma unroll
    for (int i = 0; i < 8; ++i) {
        int co = ty * 8 + i;
        float iv = gg[co] / sqrtf(vv[co] + EPSBN);
        inv_[i] = iv;
        bia_[i] = bb[co] - mm[co] * iv;
    }
#pragma unroll
    for (int j = 0; j < 8; ++j) {
        int jj = blockIdx.x * 128 + tx * 8 + j;
        int nn = jj / 3136, pp = jj - nn * 3136;
        float* op = g_buf1 + nn * 401408 + pp;    // [n][128][3136]
#pragma unroll
        for (int i = 0; i < 8; ++i) {
            int co = ty * 8 + i;
            float y = acc[i][j] * inv_[i] + bia_[i];
            op[co * 3136] = fmaxf(fq(y, s), 0.f);
        }
    }
}

// ---------------------------------------------------------------------------
// Kernel 2: conv2 3x3 s2 pad1, 128->128. 9 accumulated 1x1-GEMM taps.
// j = n*784 + ho*28 + wo ; input h = 2*ho-1+kh, w = 2*wo-1+kw (halo-checked)
// ---------------------------------------------------------------------------
__global__ __launch_bounds__(256, 2)
void conv2_k(const float* __restrict__ w,
             const float* __restrict__ gg, const float* __restrict__ bb,
             const float* __restrict__ mm, const float* __restrict__ vv,
             const float* __restrict__ ss)
{
    __shared__ float As[16][128];
    __shared__ float Bs[16][128];
    const int t  = threadIdx.x;
    const int tx = t & 15, ty = t >> 4;
    const int jcol = t & 127, krow = t >> 7;
    const int jg = blockIdx.x * 128 + jcol;
    const int n  = jg / 784, p = jg - n * 784;
    const int ho = p / 28, wo = p - ho * 28;
    const int h0 = 2 * ho - 1, w0 = 2 * wo - 1;
    const float* o1n = g_buf1 + n * 401408;
    const int ai = t >> 1;
    const int ak = (t & 1) * 8;

    float acc[8][8];
#pragma unroll
    for (int i = 0; i < 8; ++i)
#pragma unroll
        for (int j = 0; j < 8; ++j) acc[i][j] = 0.f;

    for (int tap = 0; tap < 9; ++tap) {
        const int kh = tap / 3, kw = tap - kh * 3;
        const int h = h0 + kh, wd = w0 + kw;
        const bool valid = ((unsigned)h < 56u) && ((unsigned)wd < 56u);
        const int off = h * 56 + wd;
        for (int k0 = 0; k0 < 128; k0 += 16) {
#pragma unroll
            for (int r = 0; r < 8; ++r)
                As[ak + r][ai] = w[(ai * 128 + k0 + ak + r) * 9 + tap];
#pragma unroll
            for (int r = 0; r < 8; ++r) {
                int k = k0 + krow * 8 + r;
                Bs[krow * 8 + r][jcol] = valid ? o1n[k * 3136 + off] : 0.f;
            }
            GEMM_COMPUTE_STEP();
        }
    }

    const float s = *ss;
    float inv_[8], bia_[8];
#pragma unroll
    for (int i = 0; i < 8; ++i) {
        int co = ty * 8 + i;
        float iv = gg[co] / sqrtf(vv[co] + EPSBN);
        inv_[i] = iv;
        bia_[i] = bb[co] - mm[co] * iv;
    }
#pragma unroll
    for (int j = 0; j < 8; ++j) {
        int jj = blockIdx.x * 128 + tx * 8 + j;
        int nn = jj / 784, pp = jj - nn * 784;
        float* op = g_buf2 + nn * 100352 + pp;    // [n][128][784]
#pragma unroll
        for (int i = 0; i < 8; ++i) {
            int co = ty * 8 + i;
            float y = acc[i][j] * inv_[i] + bia_[i];
            op[co * 784] = fmaxf(fq(y, s), 0.f);
        }
    }
}

// ---------------------------------------------------------------------------
// Kernel 3: conv3 1x1, 128->512, no relu. Writes fq result into g_buf1
// (o1 is dead; layout [n][512][784], same 401408 stride).
// ---------------------------------------------------------------------------
__global__ __launch_bounds__(256, 2)
void conv3_k(const float* __restrict__ w,
             const float* __restrict__ gg, const float* __restrict__ bb,
             const float* __restrict__ mm, const float* __restrict__ vv,
             const float* __restrict__ ss)
{
    __shared__ float As[16][128];
    __shared__ float Bs[16][128];
    const int t  = threadIdx.x;
    const int tx = t & 15, ty = t >> 4;
    const int jcol = t & 127, krow = t >> 7;
    const int coT = blockIdx.y * 128;
    const int jg = blockIdx.x * 128 + jcol;
    const int n  = jg / 784, p = jg - n * 784;
    const float* o2b = g_buf2 + n * 100352 + p;
    const int ai = t >> 1;
    const int ak = (t & 1) * 8;

    float acc[8][8];
#pragma unroll
    for (int i = 0; i < 8; ++i)
#pragma unroll
        for (int j = 0; j < 8; ++j) acc[i][j] = 0.f;

    for (int k0 = 0; k0 < 128; k0 += 16) {
        const float* wp = w + (coT + ai) * 128 + k0 + ak;
#pragma unroll
        for (int r = 0; r < 8; ++r) As[ak + r][ai] = wp[r];
        const float* xp = o2b + (k0 + krow * 8) * 784;
#pragma unroll
        for (int r = 0; r < 8; ++r) Bs[krow * 8 + r][jcol] = xp[r * 784];
        GEMM_COMPUTE_STEP();
    }

    const float s = *ss;
    float inv_[8], bia_[8];
#pragma unroll
    for (int i = 0; i < 8; ++i) {
        int co = coT + ty * 8 + i;
        float iv = gg[co] / sqrtf(vv[co] + EPSBN);
        inv_[i] = iv;
        bia_[i] = bb[co] - mm[co] * iv;
    }
#pragma unroll
    for (int j = 0; j < 8; ++j) {
        int jj = blockIdx.x * 128 + tx * 8 + j;
        int nn = jj / 784, pp = jj - nn * 784;
        float* op = g_buf1 + nn * 401408 + (coT + ty * 8) * 784 + pp;
#pragma unroll
        for (int i = 0; i < 8; ++i) {
            float y = acc[i][j] * inv_[i] + bia_[i];
            op[i * 784] = fq(y, s);               // no relu here
        }
    }
}

// ---------------------------------------------------------------------------
// Kernel 4: shortcut 1x1 s2, 256->512, fq; out = relu(t3 + sc) -> d_out.
// Input gather: x[n][ci][2*ho][2*wo].
// ---------------------------------------------------------------------------
__global__ __launch_bounds__(256, 2)
void conv4_k(const float* __restrict__ x, const float* __restrict__ w,
             const float* __restrict__ gg, const float* __restrict__ bb,
             const float* __restrict__ mm, const float* __restrict__ vv,
             const float* __restrict__ ss, float* __restrict__ out)
{
    __shared__ float As[16][128];
    __shared__ float Bs[16][128];
    const int t  = threadIdx.x;
    const int tx = t & 15, ty = t >> 4;
    const int jcol = t & 127, krow = t >> 7;
    const int coT = blockIdx.y * 128;
    const int jg = blockIdx.x * 128 + jcol;
    const int n  = jg / 784, p = jg - n * 784;
    const int ho = p / 28, wo = p - ho * 28;
    const float* xb = x + n * 802816 + (2 * ho) * 56 + 2 * wo;
    const int ai = t >> 1;
    const int ak = (t & 1) * 8;

    float acc[8][8];
#pragma unroll
    for (int i = 0; i < 8; ++i)
#pragma unroll
        for (int j = 0; j < 8; ++j) acc[i][j] = 0.f;

    for (int k0 = 0; k0 < 256; k0 += 16) {
        const float* wp = w + (coT + ai) * 256 + k0 + ak;
#pragma unroll
        for (int r = 0; r < 8; ++r) As[ak + r][ai] = wp[r];
        const float* xp = xb + (k0 + krow * 8) * 3136;
#pragma unroll
        for (int r = 0; r < 8; ++r) Bs[krow * 8 + r][jcol] = xp[r * 3136];
        GEMM_COMPUTE_STEP();
    }

    const float s = *ss;
    float inv_[8], bia_[8];
#pragma unroll
    for (int i = 0; i < 8; ++i) {
        int co = coT + ty * 8 + i;
        float iv = gg[co] / sqrtf(vv[co] + EPSBN);
        inv_[i] = iv;
        bia_[i] = bb[co] - mm[co] * iv;
    }
#pragma unroll
    for (int j = 0; j < 8; ++j) {
        int jj = blockIdx.x * 128 + tx * 8 + j;
        int nn = jj / 784, pp = jj - nn * 784;
        int base = nn * 401408 + (coT + ty * 8) * 784 + pp;
        const float* t3 = g_buf1 + base;
        float* op = out + base;
#pragma unroll
        for (int i = 0; i < 8; ++i) {
            float y  = acc[i][j] * inv_[i] + bia_[i];
            float qs = fq(y, s);
            op[i * 784] = fmaxf(t3[i * 784] + qs, 0.f);
        }
    }
}

// ---------------------------------------------------------------------------
// Launch. Input order (metadata): x, w1,g1,b1,m1,v1,s1, w2,g2,b2,m2,v2,s2,
//                                 w3,g3,b3,m3,v3,s3, ws,gs,bs,ms,vs,ss
// ---------------------------------------------------------------------------
extern "C" void kernel_launch(void* const* d_in, const int* in_sizes, int n_in,
                              void* d_out, int out_size)
{
    const float* x  = (const float*)d_in[0];
    const float* w1 = (const float*)d_in[1];
    const float* g1 = (const float*)d_in[2];
    const float* b1 = (const float*)d_in[3];
    const float* m1 = (const float*)d_in[4];
    const float* v1 = (const float*)d_in[5];
    const float* s1 = (const float*)d_in[6];
    const float* w2 = (const float*)d_in[7];
    const float* g2 = (const float*)d_in[8];
    const float* b2 = (const float*)d_in[9];
    const float* m2 = (const float*)d_in[10];
    const float* v2 = (const float*)d_in[11];
    const float* s2 = (const float*)d_in[12];
    const float* w3 = (const float*)d_in[13];
    const float* g3 = (const float*)d_in[14];
    const float* b3 = (const float*)d_in[15];
    const float* m3 = (const float*)d_in[16];
    const float* v3 = (const float*)d_in[17];
    const float* s3 = (const float*)d_in[18];
    const float* ws = (const float*)d_in[19];
    const float* gs = (const float*)d_in[20];
    const float* bs = (const float*)d_in[21];
    const float* ms = (const float*)d_in[22];
    const float* vs = (const float*)d_in[23];
    const float* ss = (const float*)d_in[24];

    conv1_k<<<784, 256>>>(x, w1, g1, b1, m1, v1, s1);
    conv2_k<<<196, 256>>>(w2, g2, b2, m2, v2, s2);
    conv3_k<<<dim3(196, 4), 256>>>(w3, g3, b3, m3, v3, s3);
    conv4_k<<<dim3(196, 4), 256>>>(x, ws, gs, bs, ms, vs, ss, (float*)d_out);
}